// round 13
// baseline (speedup 1.0000x reference)
#include <cuda_runtime.h>
#include <cuda_fp16.h>
#include <cstdint>
#include <math.h>

#define NSAMP 8192
#define HIDN  256
#define SPC   16                 // samples per CTA
#define GRID  (NSAMP / SPC)      // 512

// Jet channels: 0=val, 1=d/dx0, 2=d/dx1, 3=d/dt, 4=dx0dx0, 5=dx0dx1, 6=dx1dx1
__device__ __align__(256) __half g_Wt[3][HIDN * HIDN];  // W^T fp16: [n][k]
__device__ double g_acc[5];
__device__ unsigned g_done = 0;

// SMEM layout: A region (112 rows x 512B, swizzled) then B double buffer
#define ABYTES 57344             // 112 * 512
#define BCH    16384             // B chunk: 256 rows x 64B (K=32)
#define SMEMT  (ABYTES + 2 * BCH)   // 90112

// ---------------------------------------------------------------------------
__device__ __forceinline__ uint32_t smem_u32(const void* p) {
    uint32_t a;
    asm("{ .reg .u64 t; cvta.to.shared.u64 t, %1; cvt.u32.u64 %0, t; }" : "=r"(a) : "l"(p));
    return a;
}
// Swizzled ROW BASES. Column offsets (< row stride) are combined with XOR,
// which provably stays inside the row (no carries, no OOB).
__device__ __forceinline__ uint32_t arow(uint32_t r) { return r * 512 ^ ((r & 7) << 4); }
__device__ __forceinline__ uint32_t brow(uint32_t r) { return r * 64  ^ ((r & 3) << 4); }

__device__ __forceinline__ void cpasync16(uint32_t s, const void* g) {
    asm volatile("cp.async.cg.shared.global [%0], [%1], 16;" :: "r"(s), "l"(g));
}
#define CP_COMMIT() asm volatile("cp.async.commit_group;" ::: "memory")

__device__ __forceinline__ void ldsm_x4(uint32_t* r, uint32_t a) {
    asm volatile("ldmatrix.sync.aligned.m8n8.x4.shared.b16 {%0,%1,%2,%3}, [%4];"
                 : "=r"(r[0]), "=r"(r[1]), "=r"(r[2]), "=r"(r[3]) : "r"(a));
}
__device__ __forceinline__ void mma16816h(uint32_t* d, const uint32_t* a,
                                          uint32_t b0, uint32_t b1) {
    asm volatile(
        "mma.sync.aligned.m16n8k16.row.col.f16.f16.f16.f16 "
        "{%0,%1}, {%2,%3,%4,%5}, {%6,%7}, {%0,%1};"
        : "+r"(d[0]), "+r"(d[1])
        : "r"(a[0]), "r"(a[1]), "r"(a[2]), "r"(a[3]), "r"(b0), "r"(b1));
}

// ---------------------------------------------------------------------------
__global__ void k_prepW(const float* __restrict__ W1, const float* __restrict__ W2,
                        const float* __restrict__ W3) {
    int w = blockIdx.z;
    const float* W = (w == 0) ? W1 : ((w == 1) ? W2 : W3);
    int n = blockIdx.x, k = threadIdx.x;
    g_Wt[w][n * HIDN + k] = __float2half(W[k * HIDN + n]);
    if (w == 0 && n == 0 && k < 5) g_acc[k] = 0.0;
}

// ---------------------------------------------------------------------------
// Fused whole-network kernel: layer0 jets -> 3x (GEMM + jet-tanh) with
// activations resident in SMEM -> physics epilogue -> global reduction.
__global__ void __launch_bounds__(256, 2) k_fused(
        const float* __restrict__ W0, const float* __restrict__ b0,
        const float* __restrict__ x,  const float* __restrict__ t,
        const float* __restrict__ b1, const float* __restrict__ b2,
        const float* __restrict__ b3,
        const float* __restrict__ W4, const float* __restrict__ b4,
        float* __restrict__ out) {
    extern __shared__ char smem[];
    uint32_t sb = smem_u32(smem);
    int tid = threadIdx.x;
    int warp = tid >> 5, lane = tid & 31;
    int n0 = blockIdx.x * SPC;

    const __half* Bws[3] = { g_Wt[0], g_Wt[1], g_Wt[2] };
    const float* biases[3] = { b1, b2, b3 };

    auto loadB = [&](const __half* Bw, int c) {
        uint32_t base = sb + ABYTES + (c & 1) * BCH;
        const __half* src = Bw + c * 32;
#pragma unroll
        for (int idx = tid; idx < 1024; idx += 256) {
            uint32_t r = idx >> 2, u = idx & 3;
            cpasync16(base + (brow(r) ^ (u * 16)), src + (size_t)r * HIDN + u * 8);
        }
        CP_COMMIT();
    };

    // prefetch layer-1 weights while computing layer-0 jets
    loadB(Bws[0], 0);
    loadB(Bws[0], 1);

    // ---- layer 0: input jets into resident A ----
    for (int i = tid; i < SPC * HIDN; i += 256) {
        int nl = i >> 8, j = i & 255;
        int n = n0 + nl;
        float x0 = x[2 * n], x1 = x[2 * n + 1], tv = t[n];
        float w0 = W0[j], w1 = W0[HIDN + j], w2 = W0[2 * HIDN + j];
        float zv = fmaf(x0, w0, fmaf(x1, w1, fmaf(tv, w2, b0[j])));
        float y = tanhf(zv);
        float yp = 1.0f - y * y;
        float ypp = -2.0f * y * yp;
        uint32_t r = nl * 7;
        uint32_t jb = j * 2;
        *(__half*)(smem + (arow(r + 0) ^ jb)) = __float2half(y);
        *(__half*)(smem + (arow(r + 1) ^ jb)) = __float2half(yp * w0);
        *(__half*)(smem + (arow(r + 2) ^ jb)) = __float2half(yp * w1);
        *(__half*)(smem + (arow(r + 3) ^ jb)) = __float2half(yp * w2);
        *(__half*)(smem + (arow(r + 4) ^ jb)) = __float2half(ypp * w0 * w0);
        *(__half*)(smem + (arow(r + 5) ^ jb)) = __float2half(ypp * w0 * w1);
        *(__half*)(smem + (arow(r + 6) ^ jb)) = __float2half(ypp * w1 * w1);
    }
    __syncthreads();

    int l8 = lane & 7;
    int qm8  = ((lane >> 3) & 1) * 8;   // +8 row for mats 1,3
    uint32_t qk16 = (lane >> 4) * 16;   // +16B (k+8) for mats 2,3

    uint32_t abase[7];
#pragma unroll
    for (int mt = 0; mt < 7; mt++)
        abase[mt] = arow(mt * 16 + qm8 + l8);
    uint32_t bbase0 = brow(warp * 32 + qm8 + l8);
    uint32_t bbase1 = brow(warp * 32 + 16 + qm8 + l8);

    // ---- 3 hidden layers ----
    for (int layer = 0; layer < 3; layer++) {
        uint32_t acc[7][4][2];
#pragma unroll
        for (int mt = 0; mt < 7; mt++)
#pragma unroll
            for (int nt = 0; nt < 4; nt++) { acc[mt][nt][0] = 0u; acc[mt][nt][1] = 0u; }

#pragma unroll 1
        for (int c = 0; c < 8; c++) {
            if (c < 7) asm volatile("cp.async.wait_group 1;" ::: "memory");
            else       asm volatile("cp.async.wait_group 0;" ::: "memory");
            __syncthreads();
            uint32_t bufb = sb + ABYTES + (c & 1) * BCH;
#pragma unroll
            for (int ks = 0; ks < 2; ks++) {
                uint32_t bcol = (ks * 32) ^ qk16;      // bits 4..5, disjoint
                uint32_t acol = (c * 64 + ks * 32) ^ qk16;  // bits 4..8
                uint32_t bf0[4], bf1[4];
                ldsm_x4(bf0, bufb + (bbase0 ^ bcol));
                ldsm_x4(bf1, bufb + (bbase1 ^ bcol));
#pragma unroll
                for (int mt = 0; mt < 7; mt++) {
                    uint32_t af[4];
                    ldsm_x4(af, sb + (abase[mt] ^ acol));
                    mma16816h(acc[mt][0], af, bf0[0], bf0[2]);
                    mma16816h(acc[mt][1], af, bf0[1], bf0[3]);
                    mma16816h(acc[mt][2], af, bf1[0], bf1[2]);
                    mma16816h(acc[mt][3], af, bf1[1], bf1[3]);
                }
            }
            __syncthreads();
            if (c + 2 < 8) loadB(Bws[layer], c + 2);
            else if (c == 7 && layer < 2) {
                loadB(Bws[layer + 1], 0);
                loadB(Bws[layer + 1], 1);
            }
        }

        // stage z (pre-activation) in place over A
#pragma unroll
        for (int mt = 0; mt < 7; mt++)
#pragma unroll
            for (int nt = 0; nt < 4; nt++)
#pragma unroll
                for (int e = 0; e < 2; e++) {
                    uint32_t r = mt * 16 + (lane >> 2) + e * 8;
                    uint32_t colb = (warp * 32 + nt * 8 + ((lane & 3) << 1)) * 2;
                    *(uint32_t*)(smem + (arow(r) ^ colb)) = acc[mt][nt][e];
                }
        __syncthreads();

        // jet-tanh activation in place
        const float* bias = biases[layer];
        for (int i = tid; i < SPC * HIDN; i += 256) {
            int nl = i >> 8, j = i & 255;
            uint32_t r = nl * 7;
            uint32_t jb = j * 2;
            float zv  = __half2float(*(__half*)(smem + (arow(r + 0) ^ jb))) + bias[j];
            float zg1 = __half2float(*(__half*)(smem + (arow(r + 1) ^ jb)));
            float zg2 = __half2float(*(__half*)(smem + (arow(r + 2) ^ jb)));
            float zg3 = __half2float(*(__half*)(smem + (arow(r + 3) ^ jb)));
            float zs11 = __half2float(*(__half*)(smem + (arow(r + 4) ^ jb)));
            float zs12 = __half2float(*(__half*)(smem + (arow(r + 5) ^ jb)));
            float zs22 = __half2float(*(__half*)(smem + (arow(r + 6) ^ jb)));
            float y = tanhf(zv);
            float yp = 1.0f - y * y;
            float ypp = -2.0f * y * yp;
            *(__half*)(smem + (arow(r + 0) ^ jb)) = __float2half(y);
            *(__half*)(smem + (arow(r + 1) ^ jb)) = __float2half(yp * zg1);
            *(__half*)(smem + (arow(r + 2) ^ jb)) = __float2half(yp * zg2);
            *(__half*)(smem + (arow(r + 3) ^ jb)) = __float2half(yp * zg3);
            *(__half*)(smem + (arow(r + 4) ^ jb)) = __float2half(fmaf(ypp * zg1, zg1, yp * zs11));
            *(__half*)(smem + (arow(r + 5) ^ jb)) = __float2half(fmaf(ypp * zg1, zg2, yp * zs12));
            *(__half*)(smem + (arow(r + 6) ^ jb)) = __float2half(fmaf(ypp * zg2, zg2, yp * zs22));
        }
        __syncthreads();
    }

    // ---- physics epilogue (B region is idle scratch) ----
    float*  w4s  = (float*)(smem + ABYTES);
    float*  b4s  = (float*)(smem + ABYTES + 3072);
    double* sacc = (double*)(smem + ABYTES + 3072 + 64);
    if (tid < 5) sacc[tid] = 0.0;
    for (int i = tid; i < 768; i += 256) w4s[i] = W4[i];
    if (tid < 3) b4s[tid] = b4[tid];
    __syncthreads();

    float wreg[8][3];
#pragma unroll
    for (int i = 0; i < 8; i++) {
        int k = lane * 8 + i;
        wreg[i][0] = w4s[k * 3 + 0];
        wreg[i][1] = w4s[k * 3 + 1];
        wreg[i][2] = w4s[k * 3 + 2];
    }

    for (int s = 0; s < 2; s++) {
        int nl = warp * 2 + s;
        int n = n0 + nl;

        float o[7][3];
#pragma unroll
        for (int c = 0; c < 7; c++)
#pragma unroll
            for (int a = 0; a < 3; a++) o[c][a] = 0.0f;

#pragma unroll
        for (int c = 0; c < 7; c++) {
            int4 v = *(const int4*)(smem + (arow(nl * 7 + c) ^ (lane * 16)));
            const __half2* h2 = (const __half2*)&v;
#pragma unroll
            for (int g = 0; g < 4; g++) {
                float2 f2 = __half22float2(h2[g]);
#pragma unroll
                for (int a = 0; a < 3; a++) {
                    o[c][a] = fmaf(f2.x, wreg[2 * g][a], o[c][a]);
                    o[c][a] = fmaf(f2.y, wreg[2 * g + 1][a], o[c][a]);
                }
            }
        }
#pragma unroll
        for (int c = 0; c < 7; c++)
#pragma unroll
            for (int a = 0; a < 3; a++)
#pragma unroll
                for (int off = 16; off > 0; off >>= 1)
                    o[c][a] += __shfl_xor_sync(0xFFFFFFFFu, o[c][a], off);

        if (lane == 0) {
            float s0  = o[0][0] + b4s[0];
            float s1v = o[0][1] + b4s[1];
            float s2v = o[0][2] + b4s[2];
            float D00 = o[1][0], D01 = o[2][0], D0t = o[3][0];
            float S000 = o[4][0], S011 = o[6][0];
            float D10 = o[1][1], D11 = o[2][1];
            float S100 = o[4][1], S101 = o[5][1], S111 = o[6][1];
            float D20 = o[1][2], D21 = o[2][2];
            float S200 = o[4][2], S201 = o[5][2], S211 = o[6][2];

            float x1 = x[2 * n + 1];
            float tt = t[n];
            float q  = x1 * (x1 - 1.0f);
            float qp = 2.0f * x1 - 1.0f;
            float t3 = tt / 3.0f;

            float ux0 = t3 * q * D10;
            float ux1 = t3 * (qp * s1v + q * D11);
            float uy0 = tt * q * D20;
            float uy1 = tt * (qp * s2v + q * D21) + tt;

            float e00 = ux0, e11 = uy1, e01 = 0.5f * (ux1 + uy0);

            float ux00 = t3 * q * S100;
            float ux01 = t3 * (qp * D10 + q * S101);
            float ux11 = t3 * (2.0f * s1v + 2.0f * qp * D11 + q * S111);
            float uy00 = tt * q * S200;
            float uy01 = tt * (qp * D20 + q * S201);
            float uy11 = tt * (2.0f * s2v + 2.0f * qp * D21 + q * S211);

            float e00_0 = ux00, e00_1 = ux01;
            float e11_0 = uy01, e11_1 = uy11;
            float e01_0 = 0.5f * (ux01 + uy00);
            float e01_1 = 0.5f * (ux11 + uy01);

            float trc  = e00 + e11;
            float tr_0 = e00_0 + e11_0;
            float tr_1 = e00_1 + e11_1;

            float phi = 1.0f / (1.0f + expf(-s0));
            float sp  = phi * (1.0f - phi);
            float spp = sp * (1.0f - 2.0f * phi);
            float p0 = sp * D00, p1 = sp * D01, pt = sp * D0t;
            float p00 = spp * D00 * D00 + sp * S000;
            float p11 = spp * D01 * D01 + sp * S011;
            float lap = p00 + p11;

            float A  = fmaxf(trc, 0.0f);
            float Bn = fmaxf(-trc, 0.0f);
            float ppos = (trc > 0.0f) ? 1.0f : 0.0f;
            float pneg = (trc < 0.0f) ? 1.0f : 0.0f;
            float dd = e00 - e11;

            float omp = 1.0f - phi;
            float h   = omp * omp;
            float g   = h + 1e-6f;
            float hp0 = -2.0f * omp * p0;
            float hp1 = -2.0f * omp * p1;

            float P00 = 2.0f * A + dd;
            float P11 = 2.0f * A - dd;
            float P01 = 2.0f * e01;
            float s00 = g * P00 - 2.0f * Bn;
            float s11c = g * P11 - 2.0f * Bn;
            float s01 = g * P01;

            float P00_0 = 2.0f * ppos * tr_0 + (e00_0 - e11_0);
            float P11_1 = 2.0f * ppos * tr_1 - (e00_1 - e11_1);
            float P01_0 = 2.0f * e01_0;
            float P01_1 = 2.0f * e01_1;

            float s00_0 = hp0 * P00 + g * P00_0 + 2.0f * pneg * tr_0;
            float s11_1 = hp1 * P11 + g * P11_1 + 2.0f * pneg * tr_1;
            float s01_0 = hp0 * P01 + g * P01_0;
            float s01_1 = hp1 * P01 + g * P01_1;

            float res0 = hp0 * s00 + h * s00_0 + hp1 * s01 + h * s01_1;
            float res1 = hp0 * s01 + h * s01_0 + hp1 * s11c + h * s11_1;

            float psip = A * A + 0.5f * dd * dd + 2.0f * e01 * e01;
            float psin = Bn * Bn;

            const float GCc = 0.0027f, Lc = 0.02f;
            float pf = GCc * (phi / Lc - Lc * lap) - 2.0f * omp * psip;
            float dphidt = pt;
            bool mask_pos = (fabsf(dphidt) <= 1e-3f) && (fabsf(phi - 1.0f) > 1e-3f);
            bool mask_neg = (fabsf(phi - 1.0f) <= 1e-3f);
            float respf = mask_pos ? fmaxf(-pf, 0.0f) : (mask_neg ? fmaxf(pf, 0.0f) : pf);

            float rese = omp * 2.0f * psip + psin
                       + GCc * (phi * phi / (2.0f * Lc) + 0.5f * Lc * (p0 * p0 + p1 * p1));
            float rirr = fmaxf(-dphidt, 0.0f);

            atomicAdd(&sacc[0], (double)(res0 * res0));
            atomicAdd(&sacc[1], (double)(res1 * res1));
            atomicAdd(&sacc[2], (double)(respf * respf));
            atomicAdd(&sacc[3], (double)rese);
            atomicAdd(&sacc[4], (double)rirr);
        }
    }
    __syncthreads();
    if (tid < 5) atomicAdd(&g_acc[tid], sacc[tid]);

    // last CTA finalizes outputs
    if (tid == 0) {
        __threadfence();
        unsigned v = atomicAdd(&g_done, 1u);
        if (v == gridDim.x - 1) {
            g_done = 0;   // reset for graph replay
            double S0 = g_acc[0], S1 = g_acc[1], Spf = g_acc[2];
            double Se = g_acc[3], Si = g_acc[4];
            double Nn = (double)NSAMP;
            double mse0 = S0 / Nn, mse1 = S1 / Nn;
            double m  = 0.5 * (mse0 + mse1);
            double w0 = m / (mse0 + 1e-6);
            double w1 = m / (mse1 + 1e-6);
            out[0] = (float)(w0 * mse0 + w1 * mse1);
            out[1] = (float)(Spf / Nn);
            out[2] = (float)log(Se);
            out[3] = (float)(Si / Nn);
        }
    }
}

// ---------------------------------------------------------------------------
extern "C" void kernel_launch(void* const* d_in, const int* in_sizes, int n_in,
                              void* d_out, int out_size) {
    const float *W[5], *b[5];
    if (n_in >= 2 && in_sizes[1] == HIDN) {
        for (int i = 0; i < 5; i++) {
            W[i] = (const float*)d_in[2 * i];
            b[i] = (const float*)d_in[2 * i + 1];
        }
    } else {
        for (int i = 0; i < 5; i++) {
            W[i] = (const float*)d_in[i];
            b[i] = (const float*)d_in[5 + i];
        }
    }
    const float* x = (const float*)d_in[10];
    const float* t = (const float*)d_in[11];

    static bool attr_done = false;
    if (!attr_done) {
        cudaFuncSetAttribute(k_fused, cudaFuncAttributeMaxDynamicSharedMemorySize, SMEMT);
        attr_done = true;
    }

    k_prepW<<<dim3(HIDN, 1, 3), HIDN>>>(W[1], W[2], W[3]);
    k_fused<<<GRID, 256, SMEMT>>>(W[0], b[0], x, t, b[1], b[2], b[3],
                                  W[4], b[4], (float*)d_out);
}